// round 14
// baseline (speedup 1.0000x reference)
#include <cuda_runtime.h>
#include <cuda_bf16.h>
#include <math.h>

#define TT 64
#define BB 128
#define NN 2048

// Single fused kernel: no prep pass, no inter-kernel gap. Each thread owns
// 2 consecutive neurons of one batch row, carries (v,y) in registers across
// T=64 steps. W[t,n] = 1 - beta*(1 - sigmoid(cond[t,n])) is computed INLINE
// but PIPELINED ONE STEP AHEAD: the sigmoid for step t+1 runs while step t's
// loads are still settling, keeping MUFU latency off the per-step critical
// path. tx loads L2-allocating (__ldg, 64MB fits 126MB L2 across replays);
// out stores evict-first (__stcs).

__device__ __forceinline__ float sigm_fast(float x) {
    return __fdividef(1.0f, 1.0f + __expf(-x));
}

__global__ void __launch_bounds__(128)
glif_fused(const float* __restrict__ tx,
           const float* __restrict__ alpha,
           const float* __restrict__ beta,
           const float* __restrict__ gamma,
           const float* __restrict__ tau,
           const float* __restrict__ Vth,
           const float* __restrict__ leak,
           const float* __restrict__ reVth,
           const float* __restrict__ cond,
           float* __restrict__ out) {
    const int tid = blockIdx.x * blockDim.x + threadIdx.x;  // 0 .. B*N/2-1
    const int n2  = tid & (NN / 2 - 1);                     // float2 group within N

    const float2* __restrict__ tx2 = reinterpret_cast<const float2*>(tx);
    const float2* __restrict__ cd2 = reinterpret_cast<const float2*>(cond);
    float2* __restrict__ out2      = reinterpret_cast<float2*>(out);

    // Per-neuron fused constants (once per thread; ~30 MUFU total)
    const float2 av = __ldg(&reinterpret_cast<const float2*>(alpha)[n2]);
    const float2 bv = __ldg(&reinterpret_cast<const float2*>(beta)[n2]);
    const float2 gv = __ldg(&reinterpret_cast<const float2*>(gamma)[n2]);
    const float2 tv = __ldg(&reinterpret_cast<const float2*>(tau)[n2]);
    const float2 vv = __ldg(&reinterpret_cast<const float2*>(Vth)[n2]);
    const float2 lv = __ldg(&reinterpret_cast<const float2*>(leak)[n2]);
    const float2 rv = __ldg(&reinterpret_cast<const float2*>(reVth)[n2]);

    float decx, decy, ddx, ddy, lkx, lky, rsx, rsy, vthx, vthy, bex, bey, obx, oby;
    {
        float al = sigm_fast(av.x), ga = sigm_fast(gv.x);
        float d  = 1.0f - al * (1.0f - sigm_fast(tv.x));
        decx = d;
        ddx  = d * (1.0f - ga) - d;          // decg - dec
        lkx  = (1.0f - al) * sigm_fast(lv.x);
        rsx  = (1.0f - ga) * sigm_fast(rv.x);
        vthx = sigm_fast(vv.x);
        bex  = sigm_fast(bv.x);
        obx  = 1.0f - bex;                   // w = fma(be, sigm(c), 1-be)
    }
    {
        float al = sigm_fast(av.y), ga = sigm_fast(gv.y);
        float d  = 1.0f - al * (1.0f - sigm_fast(tv.y));
        decy = d;
        ddy  = d * (1.0f - ga) - d;
        lky  = (1.0f - al) * sigm_fast(lv.y);
        rsy  = (1.0f - ga) * sigm_fast(rv.y);
        vthy = sigm_fast(vv.y);
        bey  = sigm_fast(bv.y);
        oby  = 1.0f - bey;
    }

    float2 v = make_float2(0.f, 0.f);
    float2 y = make_float2(0.f, 0.f);

    const int stride = BB * NN / 2;   // float2 stride per timestep
    const int wstr   = NN / 2;

    // Prime: load x(0), compute w(0) from cond(0)
    float2 x = __ldg(&tx2[tid]);
    float wx, wy;
    {
        float2 c0 = __ldg(&cd2[n2]);
        wx = fmaf(bex, sigm_fast(c0.x), obx);
        wy = fmaf(bey, sigm_fast(c0.y), oby);
    }

    #pragma unroll 8
    for (int t = 0; t < TT; ++t) {
        // Prefetch t+1 loads AND compute w(t+1) now — both independent of
        // the v/y dependency chain; MUFU latency overlaps step t's stalls.
        float2 xn;
        float wnx, wny;
        if (t + 1 < TT) {
            xn = __ldg(&tx2[(t + 1) * stride + tid]);
            float2 cn = __ldg(&cd2[(t + 1) * wstr + n2]);
            wnx = fmaf(bex, sigm_fast(cn.x), obx);
            wny = fmaf(bey, sigm_fast(cn.y), oby);
        }

        // lane 0
        {
            float dv = fmaf(y.x, ddx, decx);
            float cc = fmaf(y.x, -rsx, fmaf(x.x, wx, -lkx));
            v.x = fmaf(dv, v.x, cc);
            y.x = (v.x > vthx) ? 1.0f : 0.0f;
        }
        // lane 1
        {
            float dv = fmaf(y.y, ddy, decy);
            float cc = fmaf(y.y, -rsy, fmaf(x.y, wy, -lky));
            v.y = fmaf(dv, v.y, cc);
            y.y = (v.y > vthy) ? 1.0f : 0.0f;
        }

        __stcs(&out2[t * stride + tid], y);
        x = xn;
        wx = wnx;
        wy = wny;
    }
}

extern "C" void kernel_launch(void* const* d_in, const int* in_sizes, int n_in,
                              void* d_out, int out_size) {
    // metadata order: tx, alpha, beta, gamma, tau, Vth, leak, reVth, conduct
    const float* tx    = (const float*)d_in[0];
    const float* alpha = (const float*)d_in[1];
    const float* beta  = (const float*)d_in[2];
    const float* gamma = (const float*)d_in[3];
    const float* tau   = (const float*)d_in[4];
    const float* Vth   = (const float*)d_in[5];
    const float* leak  = (const float*)d_in[6];
    const float* reVth = (const float*)d_in[7];
    const float* cond  = (const float*)d_in[8];
    float* out = (float*)d_out;

    int total = BB * NN / 2;   // 131072 threads
    int blk = 128;
    glif_fused<<<total / blk, blk>>>(tx, alpha, beta, gamma, tau, Vth, leak,
                                     reVth, cond, out);
}

// round 15
// speedup vs baseline: 1.1379x; 1.1379x over previous
#include <cuda_runtime.h>
#include <cuda_bf16.h>
#include <math.h>

#define TT 64
#define BB 128
#define NN 2048

// Single fused kernel, CTA = 4 batch rows x 64 neurons (1024 CTAs x 128 thr).
// Prologue: the CTA's W tile (64t x 64n, 16KB smem) is computed ONCE from
// cond via MUFU.TANH sigmoids (32/thread) — removing the 128x-redundant
// inline transcendental work that sank R13/R14. Scan: register-resident
// (v,y) over T=64; w via conflict-free LDS; x via __ldg (tx 64MB stays
// L2-resident across graph replays); out via __stcs (evict-first).

__device__ __forceinline__ float sigm_fast(float x) {
    return __fdividef(1.0f, 1.0f + __expf(-x));
}
// sigmoid(x) = 0.5*tanh(x/2) + 0.5  -> single MUFU.TANH
__device__ __forceinline__ float sigm_tanh(float x) {
    return fmaf(0.5f, tanhf(0.5f * x), 0.5f);
}

__global__ void __launch_bounds__(128)
glif_fused(const float* __restrict__ tx,
           const float* __restrict__ alpha,
           const float* __restrict__ beta,
           const float* __restrict__ gamma,
           const float* __restrict__ tau,
           const float* __restrict__ Vth,
           const float* __restrict__ leak,
           const float* __restrict__ reVth,
           const float* __restrict__ cond,
           float* __restrict__ out) {
    __shared__ __align__(16) float s_w[TT * 64];   // [t][64n] 16KB
    __shared__ float s_be[64];                     // sigmoid(beta) per neuron col

    const int tid   = threadIdx.x;
    const int lane  = tid & 31;
    const int wid   = tid >> 5;                 // 0..3 -> batch row within CTA
    const int n_grp = blockIdx.x & 31;          // 64-neuron slice
    const int b_grp = blockIdx.x >> 5;          // 4-batch-row slice

    const int n2g    = n_grp * 32 + lane;       // global float2 neuron index
    const int b      = b_grp * 4 + wid;
    const int xoff   = b * (NN / 2) + n2g;      // float2 offset within one step
    const int stride = BB * NN / 2;             // float2 stride per timestep

    const float2* __restrict__ tx2 = reinterpret_cast<const float2*>(tx);
    float2* __restrict__ out2      = reinterpret_cast<float2*>(out);

    // Prefetch x(0) early — independent of everything below.
    float2 x = __ldg(&tx2[xoff]);

    // --- Prologue 1: sigmoid(beta) for this CTA's 64 neurons ---
    if (tid < 64) s_be[tid] = sigm_tanh(__ldg(&beta[n_grp * 64 + tid]));
    __syncthreads();

    // --- Prologue 2: W tile, 32 cells per thread ---
    {
        const float* __restrict__ csrc = cond + n_grp * 64;
        #pragma unroll
        for (int i = 0; i < 32; ++i) {
            int lin = i * 128 + tid;            // 0..4095
            int row = lin >> 6;                 // t
            int col = lin & 63;                 // neuron within 64
            float sc = sigm_tanh(__ldg(&csrc[row * NN + col]));
            float be = s_be[col];
            s_w[lin] = fmaf(be, sc, 1.0f - be); // 1 - be*(1-sc)
        }
    }

    // --- Per-neuron params (redundant across 4 warps; trivial) ---
    const float2 av = __ldg(&reinterpret_cast<const float2*>(alpha)[n2g]);
    const float2 gv = __ldg(&reinterpret_cast<const float2*>(gamma)[n2g]);
    const float2 tv = __ldg(&reinterpret_cast<const float2*>(tau)[n2g]);
    const float2 vv = __ldg(&reinterpret_cast<const float2*>(Vth)[n2g]);
    const float2 lv = __ldg(&reinterpret_cast<const float2*>(leak)[n2g]);
    const float2 rv = __ldg(&reinterpret_cast<const float2*>(reVth)[n2g]);

    float decx, decy, ddx, ddy, lkx, lky, rsx, rsy, vthx, vthy;
    {
        float al = sigm_fast(av.x), ga = sigm_fast(gv.x);
        float d  = 1.0f - al * (1.0f - sigm_fast(tv.x));
        decx = d;
        ddx  = -d * ga;                        // decg - dec
        lkx  = (1.0f - al) * sigm_fast(lv.x);
        rsx  = (1.0f - ga) * sigm_fast(rv.x);
        vthx = sigm_fast(vv.x);
    }
    {
        float al = sigm_fast(av.y), ga = sigm_fast(gv.y);
        float d  = 1.0f - al * (1.0f - sigm_fast(tv.y));
        decy = d;
        ddy  = -d * ga;
        lky  = (1.0f - al) * sigm_fast(lv.y);
        rsy  = (1.0f - ga) * sigm_fast(rv.y);
        vthy = sigm_fast(vv.y);
    }

    float2 v = make_float2(0.f, 0.f);
    float2 y = make_float2(0.f, 0.f);

    __syncthreads();   // W tile ready

    const float2* __restrict__ s_w2 = reinterpret_cast<const float2*>(s_w);

    #pragma unroll 8
    for (int t = 0; t < TT; ++t) {
        // Prefetch x(t+1) before touching the dependency chain
        float2 xn;
        if (t + 1 < TT) xn = __ldg(&tx2[(t + 1) * stride + xoff]);

        const float2 w = s_w2[t * 32 + lane];

        // lane 0
        {
            float dv = fmaf(y.x, ddx, decx);
            float cc = fmaf(y.x, -rsx, fmaf(x.x, w.x, -lkx));
            v.x = fmaf(dv, v.x, cc);
            y.x = (v.x > vthx) ? 1.0f : 0.0f;
        }
        // lane 1
        {
            float dv = fmaf(y.y, ddy, decy);
            float cc = fmaf(y.y, -rsy, fmaf(x.y, w.y, -lky));
            v.y = fmaf(dv, v.y, cc);
            y.y = (v.y > vthy) ? 1.0f : 0.0f;
        }

        __stcs(&out2[t * stride + xoff], y);
        x = xn;
    }
}

extern "C" void kernel_launch(void* const* d_in, const int* in_sizes, int n_in,
                              void* d_out, int out_size) {
    // metadata order: tx, alpha, beta, gamma, tau, Vth, leak, reVth, conduct
    const float* tx    = (const float*)d_in[0];
    const float* alpha = (const float*)d_in[1];
    const float* beta  = (const float*)d_in[2];
    const float* gamma = (const float*)d_in[3];
    const float* tau   = (const float*)d_in[4];
    const float* Vth   = (const float*)d_in[5];
    const float* leak  = (const float*)d_in[6];
    const float* reVth = (const float*)d_in[7];
    const float* cond  = (const float*)d_in[8];
    float* out = (float*)d_out;

    // 32 b-groups x 32 n-groups = 1024 CTAs of 128 threads
    glif_fused<<<1024, 128>>>(tx, alpha, beta, gamma, tau, Vth, leak,
                              reVth, cond, out);
}

// round 16
// speedup vs baseline: 1.1644x; 1.0233x over previous
#include <cuda_runtime.h>
#include <cuda_bf16.h>
#include <math.h>

#define TT 64
#define BB 128
#define NN 2048

// Single fused kernel, CTA = 8 batch rows x 64 neurons (512 CTAs x 256 thr).
// Prologue: the CTA's W tile (64t x 64n, 16KB smem) is computed ONCE from
// cond via MUFU.TANH sigmoids (16/thread; col = tid&63 is fixed per thread,
// so sigmoid(beta) lives in a register -> single __syncthreads). Scan:
// register-resident (v,y) over T=64; w via conflict-free LDS; x via __ldg
// (tx 64MB stays L2-resident across graph replays); out via __stcs.

__device__ __forceinline__ float sigm_fast(float x) {
    return __fdividef(1.0f, 1.0f + __expf(-x));
}
// sigmoid(x) = 0.5*tanh(x/2) + 0.5  -> single MUFU.TANH
__device__ __forceinline__ float sigm_tanh(float x) {
    return fmaf(0.5f, tanhf(0.5f * x), 0.5f);
}

__global__ void __launch_bounds__(256)
glif_fused(const float* __restrict__ tx,
           const float* __restrict__ alpha,
           const float* __restrict__ beta,
           const float* __restrict__ gamma,
           const float* __restrict__ tau,
           const float* __restrict__ Vth,
           const float* __restrict__ leak,
           const float* __restrict__ reVth,
           const float* __restrict__ cond,
           float* __restrict__ out) {
    __shared__ __align__(16) float s_w[TT * 64];   // [t][64n] 16KB

    const int tid   = threadIdx.x;                 // 0..255
    const int lane  = tid & 31;
    const int wid   = tid >> 5;                    // 0..7 -> batch row within CTA
    const int n_grp = blockIdx.x & 31;             // 64-neuron slice
    const int b_grp = blockIdx.x >> 5;             // 8-batch-row slice (0..15)

    const int n2g    = n_grp * 32 + lane;          // global float2 neuron index
    const int b      = b_grp * 8 + wid;
    const int xoff   = b * (NN / 2) + n2g;         // float2 offset within one step
    const int stride = BB * NN / 2;                // float2 stride per timestep

    const float2* __restrict__ tx2 = reinterpret_cast<const float2*>(tx);
    float2* __restrict__ out2      = reinterpret_cast<float2*>(out);

    // Prefetch x(0) early — independent of everything below.
    float2 x = __ldg(&tx2[xoff]);

    // --- Prologue: W tile, 16 cells per thread; col fixed = tid & 63 ---
    {
        const int col = tid & 63;
        const float be = sigm_tanh(__ldg(&beta[n_grp * 64 + col]));
        const float ob = 1.0f - be;
        const float* __restrict__ csrc = cond + n_grp * 64 + col;
        #pragma unroll
        for (int i = 0; i < 16; ++i) {
            int row = i * 4 + (tid >> 6);          // 0..63
            float sc = sigm_tanh(__ldg(&csrc[row * NN]));
            s_w[row * 64 + col] = fmaf(be, sc, ob); // 1 - be*(1-sc)
        }
    }

    // --- Per-neuron params (redundant across 8 warps; trivial) ---
    const float2 av = __ldg(&reinterpret_cast<const float2*>(alpha)[n2g]);
    const float2 gv = __ldg(&reinterpret_cast<const float2*>(gamma)[n2g]);
    const float2 tv = __ldg(&reinterpret_cast<const float2*>(tau)[n2g]);
    const float2 vv = __ldg(&reinterpret_cast<const float2*>(Vth)[n2g]);
    const float2 lv = __ldg(&reinterpret_cast<const float2*>(leak)[n2g]);
    const float2 rv = __ldg(&reinterpret_cast<const float2*>(reVth)[n2g]);

    float decx, decy, ddx, ddy, lkx, lky, rsx, rsy, vthx, vthy;
    {
        float al = sigm_fast(av.x), ga = sigm_fast(gv.x);
        float d  = 1.0f - al * (1.0f - sigm_fast(tv.x));
        decx = d;
        ddx  = -d * ga;                        // decg - dec
        lkx  = (1.0f - al) * sigm_fast(lv.x);
        rsx  = (1.0f - ga) * sigm_fast(rv.x);
        vthx = sigm_fast(vv.x);
    }
    {
        float al = sigm_fast(av.y), ga = sigm_fast(gv.y);
        float d  = 1.0f - al * (1.0f - sigm_fast(tv.y));
        decy = d;
        ddy  = -d * ga;
        lky  = (1.0f - al) * sigm_fast(lv.y);
        rsy  = (1.0f - ga) * sigm_fast(rv.y);
        vthy = sigm_fast(vv.y);
    }

    float2 v = make_float2(0.f, 0.f);
    float2 y = make_float2(0.f, 0.f);

    __syncthreads();   // W tile ready

    const float2* __restrict__ s_w2 = reinterpret_cast<const float2*>(s_w);

    #pragma unroll 8
    for (int t = 0; t < TT; ++t) {
        // Prefetch x(t+1) before touching the dependency chain
        float2 xn;
        if (t + 1 < TT) xn = __ldg(&tx2[(t + 1) * stride + xoff]);

        const float2 w = s_w2[t * 32 + lane];

        // lane 0
        {
            float dv = fmaf(y.x, ddx, decx);
            float cc = fmaf(y.x, -rsx, fmaf(x.x, w.x, -lkx));
            v.x = fmaf(dv, v.x, cc);
            y.x = (v.x > vthx) ? 1.0f : 0.0f;
        }
        // lane 1
        {
            float dv = fmaf(y.y, ddy, decy);
            float cc = fmaf(y.y, -rsy, fmaf(x.y, w.y, -lky));
            v.y = fmaf(dv, v.y, cc);
            y.y = (v.y > vthy) ? 1.0f : 0.0f;
        }

        __stcs(&out2[t * stride + xoff], y);
        x = xn;
    }
}

extern "C" void kernel_launch(void* const* d_in, const int* in_sizes, int n_in,
                              void* d_out, int out_size) {
    // metadata order: tx, alpha, beta, gamma, tau, Vth, leak, reVth, conduct
    const float* tx    = (const float*)d_in[0];
    const float* alpha = (const float*)d_in[1];
    const float* beta  = (const float*)d_in[2];
    const float* gamma = (const float*)d_in[3];
    const float* tau   = (const float*)d_in[4];
    const float* Vth   = (const float*)d_in[5];
    const float* leak  = (const float*)d_in[6];
    const float* reVth = (const float*)d_in[7];
    const float* cond  = (const float*)d_in[8];
    float* out = (float*)d_out;

    // 16 b-groups x 32 n-groups = 512 CTAs of 256 threads
    glif_fused<<<512, 256>>>(tx, alpha, beta, gamma, tau, Vth, leak,
                             reVth, cond, out);
}

// round 17
// speedup vs baseline: 1.2243x; 1.0514x over previous
#include <cuda_runtime.h>
#include <cuda_bf16.h>
#include <math.h>
#include <cstdint>

#define TT 64
#define BB 128
#define NN 2048
#define THREADS 256
#define DEPTH 4      // x-stream smem ring stages (3 outstanding)

// Single fused kernel, CTA = 8 batch rows x 64 neurons (512 CTAs x 256 thr).
// W tile (64t x 64n, 16KB) computed once per CTA into smem (MUFU.TANH).
// The x stream is pipelined via cp.async.ca into a 4-stage smem ring:
// 3 steps permanently in flight per thread (~21KB/SM reads outstanding)
// to cover L2-hit latency — no register scoreboard pressure, no syncthreads
// in the loop (each thread reads only its own slot). tx stays L2-resident
// across graph replays (.ca). out stores evict-first (__stcs).

__device__ __forceinline__ float sigm_fast(float x) {
    return __fdividef(1.0f, 1.0f + __expf(-x));
}
// sigmoid(x) = 0.5*tanh(x/2) + 0.5  -> single MUFU.TANH
__device__ __forceinline__ float sigm_tanh(float x) {
    return fmaf(0.5f, tanhf(0.5f * x), 0.5f);
}

__device__ __forceinline__ void cp_async8(void* smem_dst, const void* gmem_src) {
    uint32_t s = (uint32_t)__cvta_generic_to_shared(smem_dst);
    asm volatile("cp.async.ca.shared.global [%0], [%1], 8;"
                 :: "r"(s), "l"(gmem_src) : "memory");
}
__device__ __forceinline__ void cp_commit() {
    asm volatile("cp.async.commit_group;" ::: "memory");
}
template <int N_>
__device__ __forceinline__ void cp_wait() {
    asm volatile("cp.async.wait_group %0;" :: "n"(N_) : "memory");
}

__global__ void __launch_bounds__(THREADS)
glif_fused(const float* __restrict__ tx,
           const float* __restrict__ alpha,
           const float* __restrict__ beta,
           const float* __restrict__ gamma,
           const float* __restrict__ tau,
           const float* __restrict__ Vth,
           const float* __restrict__ leak,
           const float* __restrict__ reVth,
           const float* __restrict__ cond,
           float* __restrict__ out) {
    __shared__ __align__(16) float  s_w[TT * 64];          // 16KB W tile
    __shared__ __align__(16) float2 s_x[DEPTH][THREADS];   // 8KB x ring

    const int tid   = threadIdx.x;                 // 0..255
    const int lane  = tid & 31;
    const int wid   = tid >> 5;                    // 0..7 -> batch row within CTA
    const int n_grp = blockIdx.x & 31;             // 64-neuron slice
    const int b_grp = blockIdx.x >> 5;             // 8-batch-row slice (0..15)

    const int n2g    = n_grp * 32 + lane;          // global float2 neuron index
    const int b      = b_grp * 8 + wid;
    const int xoff   = b * (NN / 2) + n2g;         // float2 offset within one step
    const int stride = BB * NN / 2;                // float2 stride per timestep

    const float2* __restrict__ tx2 = reinterpret_cast<const float2*>(tx);
    float2* __restrict__ out2      = reinterpret_cast<float2*>(out);

    // Start the x pipeline immediately: stages for t = 0,1,2.
    #pragma unroll
    for (int s = 0; s < DEPTH - 1; ++s) {
        cp_async8(&s_x[s][tid], &tx2[s * stride + xoff]);
        cp_commit();
    }

    // --- Prologue: W tile, 16 cells per thread; col fixed = tid & 63 ---
    {
        const int col = tid & 63;
        const float be = sigm_tanh(__ldg(&beta[n_grp * 64 + col]));
        const float ob = 1.0f - be;
        const float* __restrict__ csrc = cond + n_grp * 64 + col;
        #pragma unroll
        for (int i = 0; i < 16; ++i) {
            int row = i * 4 + (tid >> 6);          // 0..63
            float sc = sigm_tanh(__ldg(&csrc[row * NN]));
            s_w[row * 64 + col] = fmaf(be, sc, ob); // 1 - be*(1-sc)
        }
    }

    // --- Per-neuron params (redundant across 8 warps; trivial) ---
    const float2 av = __ldg(&reinterpret_cast<const float2*>(alpha)[n2g]);
    const float2 gv = __ldg(&reinterpret_cast<const float2*>(gamma)[n2g]);
    const float2 tv = __ldg(&reinterpret_cast<const float2*>(tau)[n2g]);
    const float2 vv = __ldg(&reinterpret_cast<const float2*>(Vth)[n2g]);
    const float2 lv = __ldg(&reinterpret_cast<const float2*>(leak)[n2g]);
    const float2 rv = __ldg(&reinterpret_cast<const float2*>(reVth)[n2g]);

    float decx, decy, ddx, ddy, lkx, lky, rsx, rsy, vthx, vthy;
    {
        float al = sigm_fast(av.x), ga = sigm_fast(gv.x);
        float d  = 1.0f - al * (1.0f - sigm_fast(tv.x));
        decx = d;
        ddx  = -d * ga;                        // decg - dec
        lkx  = (1.0f - al) * sigm_fast(lv.x);
        rsx  = (1.0f - ga) * sigm_fast(rv.x);
        vthx = sigm_fast(vv.x);
    }
    {
        float al = sigm_fast(av.y), ga = sigm_fast(gv.y);
        float d  = 1.0f - al * (1.0f - sigm_fast(tv.y));
        decy = d;
        ddy  = -d * ga;
        lky  = (1.0f - al) * sigm_fast(lv.y);
        rsy  = (1.0f - ga) * sigm_fast(rv.y);
        vthy = sigm_fast(vv.y);
    }

    float2 v = make_float2(0.f, 0.f);
    float2 y = make_float2(0.f, 0.f);

    __syncthreads();   // W tile ready (s_x slots are per-thread private)

    const float2* __restrict__ s_w2 = reinterpret_cast<const float2*>(s_w);

    #pragma unroll 4
    for (int t = 0; t < TT; ++t) {
        // Keep the pipeline full: issue stage t+3, always commit a group.
        if (t + DEPTH - 1 < TT)
            cp_async8(&s_x[(t + DEPTH - 1) & (DEPTH - 1)][tid],
                      &tx2[(t + DEPTH - 1) * stride + xoff]);
        cp_commit();
        cp_wait<DEPTH - 1>();   // group for step t complete

        const float2 x = s_x[t & (DEPTH - 1)][tid];
        const float2 w = s_w2[t * 32 + lane];

        // lane 0
        {
            float dv = fmaf(y.x, ddx, decx);
            float cc = fmaf(y.x, -rsx, fmaf(x.x, w.x, -lkx));
            v.x = fmaf(dv, v.x, cc);
            y.x = (v.x > vthx) ? 1.0f : 0.0f;
        }
        // lane 1
        {
            float dv = fmaf(y.y, ddy, decy);
            float cc = fmaf(y.y, -rsy, fmaf(x.y, w.y, -lky));
            v.y = fmaf(dv, v.y, cc);
            y.y = (v.y > vthy) ? 1.0f : 0.0f;
        }

        __stcs(&out2[t * stride + xoff], y);
    }
}

extern "C" void kernel_launch(void* const* d_in, const int* in_sizes, int n_in,
                              void* d_out, int out_size) {
    // metadata order: tx, alpha, beta, gamma, tau, Vth, leak, reVth, conduct
    const float* tx    = (const float*)d_in[0];
    const float* alpha = (const float*)d_in[1];
    const float* beta  = (const float*)d_in[2];
    const float* gamma = (const float*)d_in[3];
    const float* tau   = (const float*)d_in[4];
    const float* Vth   = (const float*)d_in[5];
    const float* leak  = (const float*)d_in[6];
    const float* reVth = (const float*)d_in[7];
    const float* cond  = (const float*)d_in[8];
    float* out = (float*)d_out;

    // 16 b-groups x 32 n-groups = 512 CTAs of 256 threads
    glif_fused<<<512, THREADS>>>(tx, alpha, beta, gamma, tau, Vth, leak,
                                 reVth, cond, out);
}